// round 14
// baseline (speedup 1.0000x reference)
#include <cuda_runtime.h>
#include <cuda_fp16.h>
#include <math.h>
#include <stdint.h>

#define NL 16
#define NT 2048
#define ND 2048
#define NR 128
#define NK 1024      // top-k capacity (T * 0.5)
#define BANDCAP 64
#define BAND_DELTA 8e-4f

// Scratch (no device allocation allowed -> __device__ globals)
__device__ float g_probs[NL * NT];
__device__ int   g_order[NL * NT];
__device__ int   g_bandcnt[NL];
__device__ int   g_band[NL * BANDCAP];

// Pre-split fp16 scratch
__device__ __half g_Hh[67108864];   // hidden fp16  [l][t][d]
__device__ __half g_Wh[67108864];   // W_s1 hi, TRANSPOSED [l][e][d]
__device__ __half g_Wl[67108864];   // W_s1 lo, TRANSPOSED [l][e][d]
__device__ __half g_R1h[4194304];   // W_r1 hi, TRANSPOSED [l][r][d]
__device__ __half g_R1l[4194304];   // W_r1 lo

// ===========================================================================
// Helpers (sm_80-compatible PTX only)
// ===========================================================================
__device__ __forceinline__ uint32_t smem_u32(const void* p) {
    uint32_t a;
    asm("{ .reg .u64 t; cvta.to.shared.u64 t, %1; cvt.u32.u64 %0, t; }" : "=r"(a) : "l"(p));
    return a;
}
__device__ __forceinline__ void ldsm_x4(uint32_t* d, uint32_t addr) {
    asm volatile("ldmatrix.sync.aligned.m8n8.x4.shared.b16 {%0,%1,%2,%3}, [%4];"
                 : "=r"(d[0]), "=r"(d[1]), "=r"(d[2]), "=r"(d[3]) : "r"(addr));
}
__device__ __forceinline__ void mma_f16(float* c, const uint32_t* a, uint32_t b0, uint32_t b1) {
    asm volatile(
        "mma.sync.aligned.m16n8k16.row.col.f32.f16.f16.f32 "
        "{%0,%1,%2,%3}, {%4,%5,%6,%7}, {%8,%9}, {%0,%1,%2,%3};"
        : "+f"(c[0]), "+f"(c[1]), "+f"(c[2]), "+f"(c[3])
        : "r"(a[0]), "r"(a[1]), "r"(a[2]), "r"(a[3]), "r"(b0), "r"(b1));
}
__device__ __forceinline__ void split2(float x, float y, uint32_t& h, uint32_t& l) {
    __half hx = __float2half_rn(x);
    __half hy = __float2half_rn(y);
    __half lx = __float2half_rn(x - __half2float(hx));
    __half ly = __float2half_rn(y - __half2float(hy));
    __half2 th = __halves2half2(hx, hy);
    __half2 tl = __halves2half2(lx, ly);
    h = *reinterpret_cast<uint32_t*>(&th);
    l = *reinterpret_cast<uint32_t*>(&tl);
}
__device__ __forceinline__ uint32_t pack_hi2(float x, float y) {
    __half2 t = __halves2half2(__float2half_rn(x), __float2half_rn(y));
    return *reinterpret_cast<uint32_t*>(&t);
}
#define CP16(d, s) asm volatile("cp.async.cg.shared.global [%0], [%1], 16;\n" :: "r"(d), "l"(s))
#define CPCOMMIT() asm volatile("cp.async.commit_group;\n" ::: "memory")
#define CPWAIT1()  asm volatile("cp.async.wait_group 1;\n" ::: "memory")

// ---------------------------------------------------------------------------
// Pre-split kernels
// ---------------------------------------------------------------------------
__global__ __launch_bounds__(256) void split_h_kernel(const float* __restrict__ h)
{
    size_t idx = ((size_t)blockIdx.x * 256 + threadIdx.x) * 4;
    float4 v = *(const float4*)(h + idx);
    uint32_t h0 = pack_hi2(v.x, v.y);
    uint32_t h1 = pack_hi2(v.z, v.w);
    *(uint2*)&g_Hh[idx] = make_uint2(h0, h1);
}

// W_s1 [l][d][e] -> g_W{h,l} transposed [l][e][d]
__global__ __launch_bounds__(256) void split_w_kernel(const float* __restrict__ W)
{
    __shared__ float s[64][129];
    const int l = blockIdx.z, kb = blockIdx.y, eb = blockIdx.x;
    const int tid = threadIdx.x;
    const float* src = W + ((size_t)l * ND + kb * 64) * ND + eb * 128;
    #pragma unroll
    for (int i = 0; i < 8; i++) {
        int idx = tid + i * 256;
        int k = idx >> 5;
        int e4 = (idx & 31) * 4;
        float4 v = *(const float4*)(src + (size_t)k * ND + e4);
        s[k][e4] = v.x; s[k][e4 + 1] = v.y; s[k][e4 + 2] = v.z; s[k][e4 + 3] = v.w;
    }
    __syncthreads();
    const int e  = tid >> 1;
    const int kh = (tid & 1) * 32;
    uint32_t hw[16], lw[16];
    #pragma unroll
    for (int j = 0; j < 16; j++)
        split2(s[kh + 2 * j][e], s[kh + 2 * j + 1][e], hw[j], lw[j]);
    size_t doff = ((size_t)l * ND + eb * 128 + e) * ND + kb * 64 + kh;
    #pragma unroll
    for (int q = 0; q < 4; q++) {
        *(uint4*)&g_Wh[doff + q * 8] = make_uint4(hw[4*q], hw[4*q+1], hw[4*q+2], hw[4*q+3]);
        *(uint4*)&g_Wl[doff + q * 8] = make_uint4(lw[4*q], lw[4*q+1], lw[4*q+2], lw[4*q+3]);
    }
}

// W_r1 [l][d][r] -> g_R1{h,l} transposed [l][r][d]
__global__ __launch_bounds__(256) void split_r1_kernel(const float* __restrict__ W)
{
    __shared__ float s[64][129];
    const int l = blockIdx.y, kb = blockIdx.x;
    const int tid = threadIdx.x;
    const float* src = W + ((size_t)l * ND + kb * 64) * NR;
    #pragma unroll
    for (int i = 0; i < 8; i++) {
        int idx = tid + i * 256;
        int k  = idx >> 5;
        int r4 = (idx & 31) * 4;
        float4 v = *(const float4*)(src + (size_t)k * NR + r4);
        s[k][r4] = v.x; s[k][r4 + 1] = v.y; s[k][r4 + 2] = v.z; s[k][r4 + 3] = v.w;
    }
    __syncthreads();
    const int r  = tid >> 1;
    const int kh = (tid & 1) * 32;
    uint32_t hw[16], lw[16];
    #pragma unroll
    for (int j = 0; j < 16; j++)
        split2(s[kh + 2 * j][r], s[kh + 2 * j + 1][r], hw[j], lw[j]);
    size_t doff = ((size_t)l * NR + r) * ND + kb * 64 + kh;
    #pragma unroll
    for (int q = 0; q < 4; q++) {
        *(uint4*)&g_R1h[doff + q * 8] = make_uint4(hw[4*q], hw[4*q+1], hw[4*q+2], hw[4*q+3]);
        *(uint4*)&g_R1l[doff + q * 8] = make_uint4(lw[4*q], lw[4*q+1], lw[4*q+2], lw[4*q+3]);
    }
}

// ===========================================================================
// Shared 2-product GEMM core (proven R11/R12 structure)
// ===========================================================================
#define KC       32
#define ASTRIDE  40
#define C_OFF_BH 10240
#define C_OFF_BL 20480
#define C_BUFB   30720
#define C_MISC   92160

#define CORE_ISSUE(cc, buf) do {                                                \
    uint32_t bb = sbase + (buf) * C_BUFB;                                       \
    const __half* pah = aH + (cc) * KC;                                         \
    const __half* pbh = bH + (cc) * KC;                                         \
    const __half* pbl = bL + (cc) * KC;                                         \
    CP16(bb + stsA,            pah); CP16(bb + stsA + 16,            pah + 8);  \
    CP16(bb + C_OFF_BH + stsA, pbh); CP16(bb + C_OFF_BH + stsA + 16, pbh + 8);  \
    CP16(bb + C_OFF_BL + stsA, pbl); CP16(bb + C_OFF_BL + stsA + 16, pbl + 8);  \
    CPCOMMIT();                                                                 \
} while (0)

// B-only issue (router: A comes via LDG+STS)
#define CORE_ISSUE_B(cc, buf) do {                                              \
    uint32_t bb = sbase + (buf) * C_BUFB;                                       \
    const __half* pbh = bH + (cc) * KC;                                         \
    const __half* pbl = bL + (cc) * KC;                                         \
    CP16(bb + C_OFF_BH + stsA, pbh); CP16(bb + C_OFF_BH + stsA + 16, pbh + 8);  \
    CP16(bb + C_OFF_BL + stsA, pbl); CP16(bb + C_OFF_BL + stsA + 16, pbl + 8);  \
    CPCOMMIT();                                                                 \
} while (0)

// convert 16 fp32 (in av[4] float4) -> fp16, store to A array of buffer
#define CORE_STS_A(buf) do {                                                    \
    uint32_t bb = sbase + (buf) * C_BUFB;                                       \
    uint32_t hw[8];                                                             \
    _Pragma("unroll")                                                           \
    for (int j = 0; j < 4; j++) {                                               \
        hw[2*j]   = pack_hi2(av[j].x, av[j].y);                                 \
        hw[2*j+1] = pack_hi2(av[j].z, av[j].w);                                 \
    }                                                                           \
    *(uint4*)((char*)sm + (bb - sbase) + stsA)      = make_uint4(hw[0], hw[1], hw[2], hw[3]); \
    *(uint4*)((char*)sm + (bb - sbase) + stsA + 16) = make_uint4(hw[4], hw[5], hw[6], hw[7]); \
} while (0)

#define CORE_COMPUTE(buf) do {                                                  \
    const uint32_t bb = sbase + (buf) * C_BUFB;                                 \
    _Pragma("unroll")                                                           \
    for (int s = 0; s < 2; s++) {                                               \
        const int k0 = s * 16;                                                  \
        uint32_t ah[4][4], bh[2][4], bl[2][4];                                  \
        const uint32_t a_ad = bb + ((m_base + frow) * ASTRIDE + k0 + fcol) * 2; \
        _Pragma("unroll")                                                       \
        for (int i = 0; i < 4; i++)                                             \
            ldsm_x4(ah[i], a_ad + i * (16 * ASTRIDE * 2));                      \
        const uint32_t b_ad = bb + C_OFF_BH + ((n_base + frow) * ASTRIDE + k0 + fcol) * 2; \
        _Pragma("unroll")                                                       \
        for (int j = 0; j < 2; j++) {                                           \
            ldsm_x4(bh[j], b_ad + j * (16 * ASTRIDE * 2));                      \
            ldsm_x4(bl[j], b_ad + (C_OFF_BL - C_OFF_BH) + j * (16 * ASTRIDE * 2)); \
        }                                                                       \
        _Pragma("unroll")                                                       \
        for (int i = 0; i < 4; i++) {                                           \
            _Pragma("unroll")                                                   \
            for (int jj = 0; jj < 2; jj++) {                                    \
                _Pragma("unroll")                                               \
                for (int hi = 0; hi < 2; hi++) {                                \
                    const int g = jj * 2 + hi;                                  \
                    mma_f16(acc[i][g], ah[i], bh[jj][hi], bh[jj][hi + 2]);      \
                    mma_f16(acc[i][g], ah[i], bl[jj][hi], bl[jj][hi + 2]);      \
                }                                                               \
            }                                                                   \
        }                                                                       \
    }                                                                           \
} while (0)

#define CORE_MAINLOOP()                                                         \
    CORE_ISSUE(0, 0); CORE_ISSUE(1, 1);                                         \
    {                                                                           \
        int cb = 0;                                                             \
        for (int c = 0; c < ND / KC; c++) {                                     \
            CPWAIT1();                                                          \
            __syncthreads();                                                    \
            CORE_COMPUTE(cb);                                                   \
            if (c + 2 < ND / KC) {                                              \
                int ib = cb + 2; if (ib >= 3) ib -= 3;                          \
                CORE_ISSUE(c + 2, ib);                                          \
            }                                                                   \
            cb = (cb == 2) ? 0 : cb + 1;                                        \
        }                                                                       \
    }

// ---------------------------------------------------------------------------
// Router GEMM (fp16 2-product, band-repaired). A loaded directly from fp32
// hidden (LDG prefetch + single-round cvt + STS) -> no split_h dependency.
// 2 CTAs/SM.
// ---------------------------------------------------------------------------
#define RT_SM    95744

__global__ __launch_bounds__(256, 2) void router_mm(
    const float* __restrict__ hidden,
    const float* __restrict__ b_r1,
    const float* __restrict__ W_r2,
    const float* __restrict__ b_r2)
{
    extern __shared__ char sm[];
    const int l   = blockIdx.y;
    const int t0  = blockIdx.x * 128;
    const int tid = threadIdx.x;
    const int w   = tid >> 5;
    const int lane = tid & 31;
    const uint32_t sbase = smem_u32(sm);

    float* sB1   = (float*)(sm + C_MISC);
    float* sW2   = (float*)(sm + C_MISC + 512);
    float* spart = (float*)(sm + C_MISC + 1024);
    if (tid < NR) {
        sB1[tid] = b_r1[l * NR + tid];
        sW2[tid] = W_r2[l * NR + tid];
    }

    const int row = tid >> 1;
    const int kh  = (tid & 1) * 16;
    const float* aF = hidden + ((size_t)l * NT + t0 + row) * ND + kh;   // fp32 A
    const __half* bH = g_R1h + ((size_t)l * NR + row) * ND + kh;
    const __half* bL = g_R1l + ((size_t)l * NR + row) * ND + kh;
    const uint32_t stsA = (uint32_t)(row * ASTRIDE + kh) * 2;

    const int wm = w & 1, wn = w >> 1;
    const int m_base = wm * 64, n_base = wn * 32;
    const int frow = lane & 15;
    const int fcol = (lane >> 4) * 8;

    float acc[4][4][4];
    #pragma unroll
    for (int i = 0; i < 4; i++)
        #pragma unroll
        for (int g = 0; g < 4; g++)
            #pragma unroll
            for (int e = 0; e < 4; e++) acc[i][g][e] = 0.f;

    float4 av[4];

    // prologue: chunks 0,1 (A by LDG+STS; B by cp.async)
    #pragma unroll
    for (int j = 0; j < 4; j++) av[j] = *(const float4*)(aF + 0 * KC + j * 4);
    CORE_STS_A(0);
    CORE_ISSUE_B(0, 0);
    #pragma unroll
    for (int j = 0; j < 4; j++) av[j] = *(const float4*)(aF + 1 * KC + j * 4);
    CORE_STS_A(1);
    CORE_ISSUE_B(1, 1);

    {
        int cb = 0;
        for (int c = 0; c < ND / KC; c++) {
            // issue LDGs for chunk c+2 early (latency hides under wait+compute)
            if (c + 2 < ND / KC) {
                #pragma unroll
                for (int j = 0; j < 4; j++)
                    av[j] = *(const float4*)(aF + (size_t)(c + 2) * KC + j * 4);
            }
            CPWAIT1();
            __syncthreads();
            if (c + 2 < ND / KC) {
                int ib = cb + 2; if (ib >= 3) ib -= 3;
                CORE_STS_A(ib);
                CORE_ISSUE_B(c + 2, ib);
            }
            CORE_COMPUTE(cb);
            cb = (cb == 2) ? 0 : cb + 1;
        }
    }

    const int tq = lane >> 2;
    const int tr = lane & 3;
    #pragma unroll
    for (int i = 0; i < 4; i++) {
        float sa = 0.f, sb = 0.f;
        #pragma unroll
        for (int g = 0; g < 4; g++) {
            const int c0 = n_base + g * 8 + tr * 2;
            const float b0 = sB1[c0], b1v = sB1[c0 + 1];
            const float w0 = sW2[c0], w1v = sW2[c0 + 1];
            sa += fmaxf(acc[i][g][0] + b0, 0.f) * w0 + fmaxf(acc[i][g][1] + b1v, 0.f) * w1v;
            sb += fmaxf(acc[i][g][2] + b0, 0.f) * w0 + fmaxf(acc[i][g][3] + b1v, 0.f) * w1v;
        }
        sa += __shfl_down_sync(0xffffffffu, sa, 2, 4);
        sa += __shfl_down_sync(0xffffffffu, sa, 1, 4);
        sb += __shfl_down_sync(0xffffffffu, sb, 2, 4);
        sb += __shfl_down_sync(0xffffffffu, sb, 1, 4);
        if (tr == 0) {
            spart[wn * 128 + m_base + i * 16 + tq]     = sa;
            spart[wn * 128 + m_base + i * 16 + tq + 8] = sb;
        }
    }
    __syncthreads();

    if (tid < 128) {
        float logit = spart[tid] + spart[128 + tid] + spart[256 + tid] + spart[384 + tid]
                    + b_r2[l];
        g_probs[l * NT + t0 + tid] = 1.0f / (1.0f + expf(-logit));
    }
}

// ---------------------------------------------------------------------------
// Top-K via exhaustive rank — 8 blocks/layer
// ---------------------------------------------------------------------------
__global__ __launch_bounds__(256) void topk_kernel()
{
    __shared__ float sp[NT];
    const int l   = blockIdx.x >> 3;
    const int seg = blockIdx.x & 7;
    for (int i = threadIdx.x; i < NT; i += 256) sp[i] = g_probs[l * NT + i];
    __syncthreads();

    const int t = seg * 256 + threadIdx.x;
    const float p = sp[t];
    int rank = 0;
    #pragma unroll 8
    for (int j = 0; j < NT; j++) {
        float q = sp[j];
        rank += (q > p) || (q == p && j < t);
    }
    g_order[l * NT + rank] = t;
}

// ---------------------------------------------------------------------------
// Find tokens within BAND_DELTA of the K-th prob
// ---------------------------------------------------------------------------
__global__ __launch_bounds__(256) void band_find_kernel()
{
    __shared__ int cnt;
    __shared__ float vK;
    const int l = blockIdx.x;
    if (threadIdx.x == 0) {
        cnt = 0;
        vK = g_probs[l * NT + g_order[l * NT + NK - 1]];
    }
    __syncthreads();
    for (int t = threadIdx.x; t < NT; t += 256) {
        float p = g_probs[l * NT + t];
        if (fabsf(p - vK) <= BAND_DELTA) {
            int i = atomicAdd(&cnt, 1);
            if (i < BANDCAP) g_band[l * BANDCAP + i] = t;
        }
    }
    __syncthreads();
    if (threadIdx.x == 0) g_bandcnt[l] = cnt < BANDCAP ? cnt : BANDCAP;
}

// ---------------------------------------------------------------------------
// Exact fp32 recompute of band tokens' probs
// ---------------------------------------------------------------------------
__global__ __launch_bounds__(128) void exact_fix_kernel(
    const float* __restrict__ hidden,
    const float* __restrict__ W_r1,
    const float* __restrict__ b_r1,
    const float* __restrict__ W_r2,
    const float* __restrict__ b_r2)
{
    const int i = blockIdx.x, l = blockIdx.y;
    if (i >= g_bandcnt[l]) return;
    const int t = g_band[l * BANDCAP + i];
    const int r = threadIdx.x;

    const float* h = hidden + ((size_t)l * NT + t) * ND;
    const float* w = W_r1 + (size_t)l * ND * NR + r;
    float acc = 0.f;
    #pragma unroll 8
    for (int d = 0; d < ND; d++) acc += h[d] * w[(size_t)d * NR];

    float v = fmaxf(acc + b_r1[l * NR + r], 0.f) * W_r2[l * NR + r];

    __shared__ float red[128];
    red[r] = v;
    __syncthreads();
    #pragma unroll
    for (int s = 64; s > 0; s >>= 1) {
        if (r < s) red[r] += red[r + s];
        __syncthreads();
    }
    if (r == 0) {
        float logit = red[0] + b_r2[l];
        g_probs[l * NT + t] = 1.0f / (1.0f + expf(-logit));
    }
}

// ---------------------------------------------------------------------------
// Copy s2 rows
// ---------------------------------------------------------------------------
__global__ __launch_bounds__(128) void copy_kernel(
    const float* __restrict__ s2, float* __restrict__ out)
{
    const int l = blockIdx.x >> 10;
    const int i = blockIdx.x & (NK - 1);
    const int t = g_order[l * NT + i];
    const float4* src = (const float4*)(s2 + ((size_t)l * NT + t) * ND);
    float4*       dst = (float4*)(out + ((size_t)l * NT + t) * ND);
    #pragma unroll
    for (int j = threadIdx.x; j < ND / 4; j += 128) dst[j] = src[j];
}

// ---------------------------------------------------------------------------
// s1 GEMM: fp16 HMMA, 2 products — proven R11/R12 version.
// ---------------------------------------------------------------------------
#define S_SM     92672

__global__ __launch_bounds__(256, 2) void s1_gemm_cp(
    const float* __restrict__ b_s1,
    float* __restrict__ out)
{
    extern __shared__ char sm[];
    const int l   = blockIdx.z;
    const int n0  = blockIdx.x * 128;
    const int r0  = blockIdx.y * 128;
    const int tid = threadIdx.x;
    const int w   = tid >> 5;
    const int lane = tid & 31;
    const uint32_t sbase = smem_u32(sm);

    int* srows = (int*)(sm + C_MISC);
    if (tid < 128) srows[tid] = g_order[l * NT + NK + r0 + tid];
    __syncthreads();

    const int row = tid >> 1;
    const int kh  = (tid & 1) * 16;
    const __half* aH = g_Hh + ((size_t)l * NT + srows[row]) * ND + kh;
    const __half* bH = g_Wh + ((size_t)l * ND + n0 + row) * ND + kh;
    const __half* bL = g_Wl + ((size_t)l * ND + n0 + row) * ND + kh;
    const uint32_t stsA = (uint32_t)(row * ASTRIDE + kh) * 2;

    const int wm = w & 1, wn = w >> 1;
    const int m_base = wm * 64, n_base = wn * 32;
    const int frow = lane & 15;
    const int fcol = (lane >> 4) * 8;

    float acc[4][4][4];
    #pragma unroll
    for (int i = 0; i < 4; i++)
        #pragma unroll
        for (int g = 0; g < 4; g++)
            #pragma unroll
            for (int e = 0; e < 4; e++) acc[i][g][e] = 0.f;

    CORE_MAINLOOP()

    const int tq = lane >> 2;
    const int tr = lane & 3;
    #pragma unroll
    for (int g = 0; g < 4; g++) {
        const int col = n_base + g * 8 + tr * 2;
        const float bx = __ldg(b_s1 + l * ND + n0 + col);
        const float by = __ldg(b_s1 + l * ND + n0 + col + 1);
        #pragma unroll
        for (int i = 0; i < 4; i++) {
            const int rl = m_base + i * 16 + tq;
            float* o0 = out + ((size_t)l * NT + srows[rl])     * ND + n0 + col;
            float* o1 = out + ((size_t)l * NT + srows[rl + 8]) * ND + n0 + col;
            *(float2*)o0 = make_float2(acc[i][g][0] + bx, acc[i][g][1] + by);
            *(float2*)o1 = make_float2(acc[i][g][2] + bx, acc[i][g][3] + by);
        }
    }
}

// ---------------------------------------------------------------------------
extern "C" void kernel_launch(void* const* d_in, const int* in_sizes, int n_in,
                              void* d_out, int out_size)
{
    const float* hidden = (const float*)d_in[0];
    const float* s2     = (const float*)d_in[1];
    const float* W_r1   = (const float*)d_in[2];
    const float* b_r1   = (const float*)d_in[3];
    const float* W_r2   = (const float*)d_in[4];
    const float* b_r2   = (const float*)d_in[5];
    const float* W_s1   = (const float*)d_in[6];
    const float* b_s1   = (const float*)d_in[7];
    float* out = (float*)d_out;

    static cudaStream_t sB = nullptr;
    static cudaEvent_t eFork = nullptr, eR1 = nullptr, eW = nullptr,
                       eOrd = nullptr, eCopy = nullptr;
    if (!sB) {
        cudaFuncSetAttribute(s1_gemm_cp, cudaFuncAttributeMaxDynamicSharedMemorySize, S_SM);
        cudaFuncSetAttribute(router_mm, cudaFuncAttributeMaxDynamicSharedMemorySize, RT_SM);
        cudaStreamCreateWithFlags(&sB, cudaStreamNonBlocking);
        cudaEventCreateWithFlags(&eFork, cudaEventDisableTiming);
        cudaEventCreateWithFlags(&eR1,   cudaEventDisableTiming);
        cudaEventCreateWithFlags(&eW,    cudaEventDisableTiming);
        cudaEventCreateWithFlags(&eOrd,  cudaEventDisableTiming);
        cudaEventCreateWithFlags(&eCopy, cudaEventDisableTiming);
    }

    // fork: side stream does split_r1 (feeds router), then split_h + split_w
    // (both feed the GEMM) — all off the critical path.
    cudaEventRecord(eFork, 0);
    cudaStreamWaitEvent(sB, eFork, 0);
    split_r1_kernel<<<dim3(32, 16), 256, 0, sB>>>(W_r1);
    cudaEventRecord(eR1, sB);
    split_h_kernel<<<65536, 256, 0, sB>>>(hidden);
    split_w_kernel<<<dim3(16, 32, 16), 256, 0, sB>>>(W_s1);
    cudaEventRecord(eW, sB);

    // main chain: router reads fp32 hidden directly
    cudaStreamWaitEvent(0, eR1, 0);
    router_mm<<<dim3(16, 16), 256, RT_SM>>>(hidden, b_r1, W_r2, b_r2);
    topk_kernel<<<NL * 8, 256>>>();
    band_find_kernel<<<NL, 256>>>();
    exact_fix_kernel<<<dim3(BANDCAP, NL), 128>>>(hidden, W_r1, b_r1, W_r2, b_r2);
    topk_kernel<<<NL * 8, 256>>>();
    cudaEventRecord(eOrd, 0);

    // side stream: copy overlaps the GEMM (disjoint output rows)
    cudaStreamWaitEvent(sB, eOrd, 0);
    copy_kernel<<<NL * NK, 128, 0, sB>>>(s2, out);
    cudaEventRecord(eCopy, sB);

    // main: GEMM needs split_h + split_w done
    cudaStreamWaitEvent(0, eW, 0);
    dim3 g(ND / 128, (NT - NK) / 128, NL);
    s1_gemm_cp<<<g, 256, S_SM>>>(b_s1, out);

    // join
    cudaStreamWaitEvent(0, eCopy, 0);
}

// round 15
// speedup vs baseline: 1.0656x; 1.0656x over previous
#include <cuda_runtime.h>
#include <cuda_fp16.h>
#include <math.h>
#include <stdint.h>

#define NL 16
#define NT 2048
#define ND 2048
#define NR 128
#define NK 1024      // top-k capacity (T * 0.5)
#define BANDCAP 64
#define BAND_DELTA 8e-4f

// Scratch (no device allocation allowed -> __device__ globals)
__device__ float g_probs[NL * NT];
__device__ int   g_order[NL * NT];
__device__ int   g_bandcnt[NL];
__device__ int   g_band[NL * BANDCAP];

// Pre-split fp16 scratch (weights only; activations converted in-kernel)
__device__ __half g_Wh[67108864];   // W_s1 hi, TRANSPOSED [l][e][d]
__device__ __half g_Wl[67108864];   // W_s1 lo, TRANSPOSED [l][e][d]
__device__ __half g_R1h[4194304];   // W_r1 hi, TRANSPOSED [l][r][d]
__device__ __half g_R1l[4194304];   // W_r1 lo

// ===========================================================================
// Helpers (sm_80-compatible PTX only)
// ===========================================================================
__device__ __forceinline__ uint32_t smem_u32(const void* p) {
    uint32_t a;
    asm("{ .reg .u64 t; cvta.to.shared.u64 t, %1; cvt.u32.u64 %0, t; }" : "=r"(a) : "l"(p));
    return a;
}
__device__ __forceinline__ void ldsm_x4(uint32_t* d, uint32_t addr) {
    asm volatile("ldmatrix.sync.aligned.m8n8.x4.shared.b16 {%0,%1,%2,%3}, [%4];"
                 : "=r"(d[0]), "=r"(d[1]), "=r"(d[2]), "=r"(d[3]) : "r"(addr));
}
__device__ __forceinline__ void mma_f16(float* c, const uint32_t* a, uint32_t b0, uint32_t b1) {
    asm volatile(
        "mma.sync.aligned.m16n8k16.row.col.f32.f16.f16.f32 "
        "{%0,%1,%2,%3}, {%4,%5,%6,%7}, {%8,%9}, {%0,%1,%2,%3};"
        : "+f"(c[0]), "+f"(c[1]), "+f"(c[2]), "+f"(c[3])
        : "r"(a[0]), "r"(a[1]), "r"(a[2]), "r"(a[3]), "r"(b0), "r"(b1));
}
__device__ __forceinline__ void split2(float x, float y, uint32_t& h, uint32_t& l) {
    __half hx = __float2half_rn(x);
    __half hy = __float2half_rn(y);
    __half lx = __float2half_rn(x - __half2float(hx));
    __half ly = __float2half_rn(y - __half2float(hy));
    __half2 th = __halves2half2(hx, hy);
    __half2 tl = __halves2half2(lx, ly);
    h = *reinterpret_cast<uint32_t*>(&th);
    l = *reinterpret_cast<uint32_t*>(&tl);
}
__device__ __forceinline__ uint32_t pack_hi2(float x, float y) {
    __half2 t = __halves2half2(__float2half_rn(x), __float2half_rn(y));
    return *reinterpret_cast<uint32_t*>(&t);
}
#define CP16(d, s) asm volatile("cp.async.cg.shared.global [%0], [%1], 16;\n" :: "r"(d), "l"(s))
#define CPCOMMIT() asm volatile("cp.async.commit_group;\n" ::: "memory")
#define CPWAIT1()  asm volatile("cp.async.wait_group 1;\n" ::: "memory")

// ---------------------------------------------------------------------------
// Pre-split kernels (weights only)
// ---------------------------------------------------------------------------
// W_s1 [l][d][e] -> g_W{h,l} transposed [l][e][d]
__global__ __launch_bounds__(256) void split_w_kernel(const float* __restrict__ W)
{
    __shared__ float s[64][129];
    const int l = blockIdx.z, kb = blockIdx.y, eb = blockIdx.x;
    const int tid = threadIdx.x;
    const float* src = W + ((size_t)l * ND + kb * 64) * ND + eb * 128;
    #pragma unroll
    for (int i = 0; i < 8; i++) {
        int idx = tid + i * 256;
        int k = idx >> 5;
        int e4 = (idx & 31) * 4;
        float4 v = *(const float4*)(src + (size_t)k * ND + e4);
        s[k][e4] = v.x; s[k][e4 + 1] = v.y; s[k][e4 + 2] = v.z; s[k][e4 + 3] = v.w;
    }
    __syncthreads();
    const int e  = tid >> 1;
    const int kh = (tid & 1) * 32;
    uint32_t hw[16], lw[16];
    #pragma unroll
    for (int j = 0; j < 16; j++)
        split2(s[kh + 2 * j][e], s[kh + 2 * j + 1][e], hw[j], lw[j]);
    size_t doff = ((size_t)l * ND + eb * 128 + e) * ND + kb * 64 + kh;
    #pragma unroll
    for (int q = 0; q < 4; q++) {
        *(uint4*)&g_Wh[doff + q * 8] = make_uint4(hw[4*q], hw[4*q+1], hw[4*q+2], hw[4*q+3]);
        *(uint4*)&g_Wl[doff + q * 8] = make_uint4(lw[4*q], lw[4*q+1], lw[4*q+2], lw[4*q+3]);
    }
}

// W_r1 [l][d][r] -> g_R1{h,l} transposed [l][r][d]
__global__ __launch_bounds__(256) void split_r1_kernel(const float* __restrict__ W)
{
    __shared__ float s[64][129];
    const int l = blockIdx.y, kb = blockIdx.x;
    const int tid = threadIdx.x;
    const float* src = W + ((size_t)l * ND + kb * 64) * NR;
    #pragma unroll
    for (int i = 0; i < 8; i++) {
        int idx = tid + i * 256;
        int k  = idx >> 5;
        int r4 = (idx & 31) * 4;
        float4 v = *(const float4*)(src + (size_t)k * NR + r4);
        s[k][r4] = v.x; s[k][r4 + 1] = v.y; s[k][r4 + 2] = v.z; s[k][r4 + 3] = v.w;
    }
    __syncthreads();
    const int r  = tid >> 1;
    const int kh = (tid & 1) * 32;
    uint32_t hw[16], lw[16];
    #pragma unroll
    for (int j = 0; j < 16; j++)
        split2(s[kh + 2 * j][r], s[kh + 2 * j + 1][r], hw[j], lw[j]);
    size_t doff = ((size_t)l * NR + r) * ND + kb * 64 + kh;
    #pragma unroll
    for (int q = 0; q < 4; q++) {
        *(uint4*)&g_R1h[doff + q * 8] = make_uint4(hw[4*q], hw[4*q+1], hw[4*q+2], hw[4*q+3]);
        *(uint4*)&g_R1l[doff + q * 8] = make_uint4(lw[4*q], lw[4*q+1], lw[4*q+2], lw[4*q+3]);
    }
}

// ===========================================================================
// Shared 2-product GEMM core. A: fp32 LDG -> single-round fp16 -> STS.
// B (hi/lo): cp.async from pre-split scratch. 3-stage pipeline, 2 CTAs/SM.
// ===========================================================================
#define KC       32
#define ASTRIDE  40
#define C_OFF_BH 10240
#define C_OFF_BL 20480
#define C_BUFB   30720
#define C_MISC   92160

// B-only issue (A comes via LDG+STS)
#define CORE_ISSUE_B(cc, buf) do {                                              \
    uint32_t bb = sbase + (buf) * C_BUFB;                                       \
    const __half* pbh = bH + (cc) * KC;                                         \
    const __half* pbl = bL + (cc) * KC;                                         \
    CP16(bb + C_OFF_BH + stsA, pbh); CP16(bb + C_OFF_BH + stsA + 16, pbh + 8);  \
    CP16(bb + C_OFF_BL + stsA, pbl); CP16(bb + C_OFF_BL + stsA + 16, pbl + 8);  \
    CPCOMMIT();                                                                 \
} while (0)

// convert 16 fp32 (in av[4] float4) -> fp16, store to A array of buffer
#define CORE_STS_A(buf) do {                                                    \
    uint32_t hw[8];                                                             \
    _Pragma("unroll")                                                           \
    for (int j = 0; j < 4; j++) {                                               \
        hw[2*j]   = pack_hi2(av[j].x, av[j].y);                                 \
        hw[2*j+1] = pack_hi2(av[j].z, av[j].w);                                 \
    }                                                                           \
    *(uint4*)((char*)sm + (buf) * C_BUFB + stsA)      = make_uint4(hw[0], hw[1], hw[2], hw[3]); \
    *(uint4*)((char*)sm + (buf) * C_BUFB + stsA + 16) = make_uint4(hw[4], hw[5], hw[6], hw[7]); \
} while (0)

#define CORE_COMPUTE(buf) do {                                                  \
    const uint32_t bb = sbase + (buf) * C_BUFB;                                 \
    _Pragma("unroll")                                                           \
    for (int s = 0; s < 2; s++) {                                               \
        const int k0 = s * 16;                                                  \
        uint32_t ah[4][4], bh[2][4], bl[2][4];                                  \
        const uint32_t a_ad = bb + ((m_base + frow) * ASTRIDE + k0 + fcol) * 2; \
        _Pragma("unroll")                                                       \
        for (int i = 0; i < 4; i++)                                             \
            ldsm_x4(ah[i], a_ad + i * (16 * ASTRIDE * 2));                      \
        const uint32_t b_ad = bb + C_OFF_BH + ((n_base + frow) * ASTRIDE + k0 + fcol) * 2; \
        _Pragma("unroll")                                                       \
        for (int j = 0; j < 2; j++) {                                           \
            ldsm_x4(bh[j], b_ad + j * (16 * ASTRIDE * 2));                      \
            ldsm_x4(bl[j], b_ad + (C_OFF_BL - C_OFF_BH) + j * (16 * ASTRIDE * 2)); \
        }                                                                       \
        _Pragma("unroll")                                                       \
        for (int i = 0; i < 4; i++) {                                           \
            _Pragma("unroll")                                                   \
            for (int jj = 0; jj < 2; jj++) {                                    \
                _Pragma("unroll")                                               \
                for (int hi = 0; hi < 2; hi++) {                                \
                    const int g = jj * 2 + hi;                                  \
                    mma_f16(acc[i][g], ah[i], bh[jj][hi], bh[jj][hi + 2]);      \
                    mma_f16(acc[i][g], ah[i], bl[jj][hi], bl[jj][hi + 2]);      \
                }                                                               \
            }                                                                   \
        }                                                                       \
    }                                                                           \
} while (0)

// Full mainloop with fp32-A path (used by both router and s1 GEMM)
#define CORE_MAINLOOP_F32A()                                                    \
    {                                                                           \
        float4 av[4];                                                           \
        _Pragma("unroll")                                                       \
        for (int j = 0; j < 4; j++) av[j] = *(const float4*)(aF + 0 * KC + j * 4); \
        CORE_STS_A(0);                                                          \
        CORE_ISSUE_B(0, 0);                                                     \
        _Pragma("unroll")                                                       \
        for (int j = 0; j < 4; j++) av[j] = *(const float4*)(aF + 1 * KC + j * 4); \
        CORE_STS_A(1);                                                          \
        CORE_ISSUE_B(1, 1);                                                     \
        int cb = 0;                                                             \
        for (int c = 0; c < ND / KC; c++) {                                     \
            if (c + 2 < ND / KC) {                                              \
                _Pragma("unroll")                                               \
                for (int j = 0; j < 4; j++)                                     \
                    av[j] = *(const float4*)(aF + (size_t)(c + 2) * KC + j * 4);\
            }                                                                   \
            CPWAIT1();                                                          \
            __syncthreads();                                                    \
            if (c + 2 < ND / KC) {                                              \
                int ib = cb + 2; if (ib >= 3) ib -= 3;                          \
                CORE_STS_A(ib);                                                 \
                CORE_ISSUE_B(c + 2, ib);                                        \
            }                                                                   \
            CORE_COMPUTE(cb);                                                   \
            cb = (cb == 2) ? 0 : cb + 1;                                        \
        }                                                                       \
    }

// ---------------------------------------------------------------------------
// Router GEMM (fp16 2-product, band-repaired). A direct from fp32 hidden.
// ---------------------------------------------------------------------------
#define RT_SM    95744

__global__ __launch_bounds__(256, 2) void router_mm(
    const float* __restrict__ hidden,
    const float* __restrict__ b_r1,
    const float* __restrict__ W_r2,
    const float* __restrict__ b_r2)
{
    extern __shared__ char sm[];
    const int l   = blockIdx.y;
    const int t0  = blockIdx.x * 128;
    const int tid = threadIdx.x;
    const int w   = tid >> 5;
    const int lane = tid & 31;
    const uint32_t sbase = smem_u32(sm);

    float* sB1   = (float*)(sm + C_MISC);
    float* sW2   = (float*)(sm + C_MISC + 512);
    float* spart = (float*)(sm + C_MISC + 1024);
    if (tid < NR) {
        sB1[tid] = b_r1[l * NR + tid];
        sW2[tid] = W_r2[l * NR + tid];
    }

    const int row = tid >> 1;
    const int kh  = (tid & 1) * 16;
    const float* aF = hidden + ((size_t)l * NT + t0 + row) * ND + kh;
    const __half* bH = g_R1h + ((size_t)l * NR + row) * ND + kh;
    const __half* bL = g_R1l + ((size_t)l * NR + row) * ND + kh;
    const uint32_t stsA = (uint32_t)(row * ASTRIDE + kh) * 2;

    const int wm = w & 1, wn = w >> 1;
    const int m_base = wm * 64, n_base = wn * 32;
    const int frow = lane & 15;
    const int fcol = (lane >> 4) * 8;

    float acc[4][4][4];
    #pragma unroll
    for (int i = 0; i < 4; i++)
        #pragma unroll
        for (int g = 0; g < 4; g++)
            #pragma unroll
            for (int e = 0; e < 4; e++) acc[i][g][e] = 0.f;

    CORE_MAINLOOP_F32A()

    const int tq = lane >> 2;
    const int tr = lane & 3;
    #pragma unroll
    for (int i = 0; i < 4; i++) {
        float sa = 0.f, sb = 0.f;
        #pragma unroll
        for (int g = 0; g < 4; g++) {
            const int c0 = n_base + g * 8 + tr * 2;
            const float b0 = sB1[c0], b1v = sB1[c0 + 1];
            const float w0 = sW2[c0], w1v = sW2[c0 + 1];
            sa += fmaxf(acc[i][g][0] + b0, 0.f) * w0 + fmaxf(acc[i][g][1] + b1v, 0.f) * w1v;
            sb += fmaxf(acc[i][g][2] + b0, 0.f) * w0 + fmaxf(acc[i][g][3] + b1v, 0.f) * w1v;
        }
        sa += __shfl_down_sync(0xffffffffu, sa, 2, 4);
        sa += __shfl_down_sync(0xffffffffu, sa, 1, 4);
        sb += __shfl_down_sync(0xffffffffu, sb, 2, 4);
        sb += __shfl_down_sync(0xffffffffu, sb, 1, 4);
        if (tr == 0) {
            spart[wn * 128 + m_base + i * 16 + tq]     = sa;
            spart[wn * 128 + m_base + i * 16 + tq + 8] = sb;
        }
    }
    __syncthreads();

    if (tid < 128) {
        float logit = spart[tid] + spart[128 + tid] + spart[256 + tid] + spart[384 + tid]
                    + b_r2[l];
        g_probs[l * NT + t0 + tid] = 1.0f / (1.0f + expf(-logit));
    }
}

// ---------------------------------------------------------------------------
// Top-K via exhaustive rank — 8 blocks/layer
// ---------------------------------------------------------------------------
__global__ __launch_bounds__(256) void topk_kernel()
{
    __shared__ float sp[NT];
    const int l   = blockIdx.x >> 3;
    const int seg = blockIdx.x & 7;
    for (int i = threadIdx.x; i < NT; i += 256) sp[i] = g_probs[l * NT + i];
    __syncthreads();

    const int t = seg * 256 + threadIdx.x;
    const float p = sp[t];
    int rank = 0;
    #pragma unroll 8
    for (int j = 0; j < NT; j++) {
        float q = sp[j];
        rank += (q > p) || (q == p && j < t);
    }
    g_order[l * NT + rank] = t;
}

// ---------------------------------------------------------------------------
// Find tokens within BAND_DELTA of the K-th prob
// ---------------------------------------------------------------------------
__global__ __launch_bounds__(256) void band_find_kernel()
{
    __shared__ int cnt;
    __shared__ float vK;
    const int l = blockIdx.x;
    if (threadIdx.x == 0) {
        cnt = 0;
        vK = g_probs[l * NT + g_order[l * NT + NK - 1]];
    }
    __syncthreads();
    for (int t = threadIdx.x; t < NT; t += 256) {
        float p = g_probs[l * NT + t];
        if (fabsf(p - vK) <= BAND_DELTA) {
            int i = atomicAdd(&cnt, 1);
            if (i < BANDCAP) g_band[l * BANDCAP + i] = t;
        }
    }
    __syncthreads();
    if (threadIdx.x == 0) g_bandcnt[l] = cnt < BANDCAP ? cnt : BANDCAP;
}

// ---------------------------------------------------------------------------
// Exact fp32 recompute of band tokens' probs
// ---------------------------------------------------------------------------
__global__ __launch_bounds__(128) void exact_fix_kernel(
    const float* __restrict__ hidden,
    const float* __restrict__ W_r1,
    const float* __restrict__ b_r1,
    const float* __restrict__ W_r2,
    const float* __restrict__ b_r2)
{
    const int i = blockIdx.x, l = blockIdx.y;
    if (i >= g_bandcnt[l]) return;
    const int t = g_band[l * BANDCAP + i];
    const int r = threadIdx.x;

    const float* h = hidden + ((size_t)l * NT + t) * ND;
    const float* w = W_r1 + (size_t)l * ND * NR + r;
    float acc = 0.f;
    #pragma unroll 8
    for (int d = 0; d < ND; d++) acc += h[d] * w[(size_t)d * NR];

    float v = fmaxf(acc + b_r1[l * NR + r], 0.f) * W_r2[l * NR + r];

    __shared__ float red[128];
    red[r] = v;
    __syncthreads();
    #pragma unroll
    for (int s = 64; s > 0; s >>= 1) {
        if (r < s) red[r] += red[r + s];
        __syncthreads();
    }
    if (r == 0) {
        float logit = red[0] + b_r2[l];
        g_probs[l * NT + t] = 1.0f / (1.0f + expf(-logit));
    }
}

// ---------------------------------------------------------------------------
// Copy s2 rows
// ---------------------------------------------------------------------------
__global__ __launch_bounds__(128) void copy_kernel(
    const float* __restrict__ s2, float* __restrict__ out)
{
    const int l = blockIdx.x >> 10;
    const int i = blockIdx.x & (NK - 1);
    const int t = g_order[l * NT + i];
    const float4* src = (const float4*)(s2 + ((size_t)l * NT + t) * ND);
    float4*       dst = (float4*)(out + ((size_t)l * NT + t) * ND);
    #pragma unroll
    for (int j = threadIdx.x; j < ND / 4; j += 128) dst[j] = src[j];
}

// ---------------------------------------------------------------------------
// s1 GEMM: fp16 HMMA, 2 products. A direct from fp32 hidden (gathered rows),
// B hi/lo via cp.async. No split_h dependency.
// ---------------------------------------------------------------------------
#define S_SM     92672

__global__ __launch_bounds__(256, 2) void s1_gemm_cp(
    const float* __restrict__ hidden,
    const float* __restrict__ b_s1,
    float* __restrict__ out)
{
    extern __shared__ char sm[];
    const int l   = blockIdx.z;
    const int n0  = blockIdx.x * 128;
    const int r0  = blockIdx.y * 128;
    const int tid = threadIdx.x;
    const int w   = tid >> 5;
    const int lane = tid & 31;
    const uint32_t sbase = smem_u32(sm);

    int* srows = (int*)(sm + C_MISC);
    if (tid < 128) srows[tid] = g_order[l * NT + NK + r0 + tid];
    __syncthreads();

    const int row = tid >> 1;
    const int kh  = (tid & 1) * 16;
    const float* aF = hidden + ((size_t)l * NT + srows[row]) * ND + kh;
    const __half* bH = g_Wh + ((size_t)l * ND + n0 + row) * ND + kh;
    const __half* bL = g_Wl + ((size_t)l * ND + n0 + row) * ND + kh;
    const uint32_t stsA = (uint32_t)(row * ASTRIDE + kh) * 2;

    const int wm = w & 1, wn = w >> 1;
    const int m_base = wm * 64, n_base = wn * 32;
    const int frow = lane & 15;
    const int fcol = (lane >> 4) * 8;

    float acc[4][4][4];
    #pragma unroll
    for (int i = 0; i < 4; i++)
        #pragma unroll
        for (int g = 0; g < 4; g++)
            #pragma unroll
            for (int e = 0; e < 4; e++) acc[i][g][e] = 0.f;

    CORE_MAINLOOP_F32A()

    const int tq = lane >> 2;
    const int tr = lane & 3;
    #pragma unroll
    for (int g = 0; g < 4; g++) {
        const int col = n_base + g * 8 + tr * 2;
        const float bx = __ldg(b_s1 + l * ND + n0 + col);
        const float by = __ldg(b_s1 + l * ND + n0 + col + 1);
        #pragma unroll
        for (int i = 0; i < 4; i++) {
            const int rl = m_base + i * 16 + tq;
            float* o0 = out + ((size_t)l * NT + srows[rl])     * ND + n0 + col;
            float* o1 = out + ((size_t)l * NT + srows[rl + 8]) * ND + n0 + col;
            *(float2*)o0 = make_float2(acc[i][g][0] + bx, acc[i][g][1] + by);
            *(float2*)o1 = make_float2(acc[i][g][2] + bx, acc[i][g][3] + by);
        }
    }
}

// ---------------------------------------------------------------------------
extern "C" void kernel_launch(void* const* d_in, const int* in_sizes, int n_in,
                              void* d_out, int out_size)
{
    const float* hidden = (const float*)d_in[0];
    const float* s2     = (const float*)d_in[1];
    const float* W_r1   = (const float*)d_in[2];
    const float* b_r1   = (const float*)d_in[3];
    const float* W_r2   = (const float*)d_in[4];
    const float* b_r2   = (const float*)d_in[5];
    const float* W_s1   = (const float*)d_in[6];
    const float* b_s1   = (const float*)d_in[7];
    float* out = (float*)d_out;

    static cudaStream_t sB = nullptr;
    static cudaEvent_t eFork = nullptr, eR1 = nullptr, eW = nullptr,
                       eOrd = nullptr, eCopy = nullptr;
    if (!sB) {
        cudaFuncSetAttribute(s1_gemm_cp, cudaFuncAttributeMaxDynamicSharedMemorySize, S_SM);
        cudaFuncSetAttribute(router_mm, cudaFuncAttributeMaxDynamicSharedMemorySize, RT_SM);
        cudaStreamCreateWithFlags(&sB, cudaStreamNonBlocking);
        cudaEventCreateWithFlags(&eFork, cudaEventDisableTiming);
        cudaEventCreateWithFlags(&eR1,   cudaEventDisableTiming);
        cudaEventCreateWithFlags(&eW,    cudaEventDisableTiming);
        cudaEventCreateWithFlags(&eOrd,  cudaEventDisableTiming);
        cudaEventCreateWithFlags(&eCopy, cudaEventDisableTiming);
    }

    // fork: side stream splits weights (router needs r1; GEMM needs W only)
    cudaEventRecord(eFork, 0);
    cudaStreamWaitEvent(sB, eFork, 0);
    split_r1_kernel<<<dim3(32, 16), 256, 0, sB>>>(W_r1);
    cudaEventRecord(eR1, sB);
    split_w_kernel<<<dim3(16, 32, 16), 256, 0, sB>>>(W_s1);
    cudaEventRecord(eW, sB);

    // main chain: router reads fp32 hidden directly
    cudaStreamWaitEvent(0, eR1, 0);
    router_mm<<<dim3(16, 16), 256, RT_SM>>>(hidden, b_r1, W_r2, b_r2);
    topk_kernel<<<NL * 8, 256>>>();
    band_find_kernel<<<NL, 256>>>();
    exact_fix_kernel<<<dim3(BANDCAP, NL), 128>>>(hidden, W_r1, b_r1, W_r2, b_r2);
    topk_kernel<<<NL * 8, 256>>>();
    cudaEventRecord(eOrd, 0);

    // side stream: copy overlaps the GEMM (disjoint output rows)
    cudaStreamWaitEvent(sB, eOrd, 0);
    copy_kernel<<<NL * NK, 128, 0, sB>>>(s2, out);
    cudaEventRecord(eCopy, sB);

    // main: GEMM needs split_w done
    cudaStreamWaitEvent(0, eW, 0);
    dim3 g(ND / 128, (NT - NK) / 128, NL);
    s1_gemm_cp<<<g, 256, S_SM>>>(hidden, b_s1, out);

    // join
    cudaStreamWaitEvent(0, eCopy, 0);
}